// round 10
// baseline (speedup 1.0000x reference)
#include <cuda_runtime.h>
#include <cuda_fp16.h>
#include <math.h>
#include <stdint.h>

#define BATCH 16384
#define D_IN  1711
#define KP1   1728                  // K padded to multiple of 32
#define ATANH_LIM (1.0f - 1e-5f)
#define MAXNORM   (1.0f - 4e-3f)

// ---------------- scratch (static device globals; no allocation) ----------------
__device__ float g_Xd[BATCH * KP1];
__device__ float g_Xt[BATCH * KP1];
__device__ float g_Wd1t[1024 * KP1];
__device__ float g_Wt1t[1024 * KP1];
__device__ float g_Wd2t[512 * 1024];
__device__ float g_Wt2t[512 * 1024];
__device__ float g_Wd3t[256 * 512];
__device__ float g_Wt3t[256 * 512];
__device__ float g_MXd[BATCH * 1024];
__device__ float g_MXt[BATCH * 1024];
__device__ float g_Yd[BATCH * 1024];
__device__ float g_Yt[BATCH * 1024];
__device__ float g_nd[BATCH];
__device__ float g_nt[BATCH];
__device__ float g_mid[BATCH * 256];
__device__ float g_nmid[BATCH];

// ---------------- block reduction (256 threads) ----------------
__device__ __forceinline__ float blockReduceSum(float v, float* red)
{
    int lane = threadIdx.x & 31;
    int w    = threadIdx.x >> 5;
    #pragma unroll
    for (int o = 16; o > 0; o >>= 1) v += __shfl_xor_sync(0xffffffffu, v, o);
    __syncthreads();
    if (lane == 0) red[w] = v;
    __syncthreads();
    float s = 0.f;
    #pragma unroll
    for (int i = 0; i < 8; i++) s += red[i];
    return s;
}

// ---------------- preprocess: per-row zscore(segments) + concat + expmap0 ----------------
__global__ void pre_kernel(const float* __restrict__ s0, int d0,
                           const float* __restrict__ s1, int d1,
                           const float* __restrict__ s2, int d2,
                           const float* __restrict__ s3, int d3,
                           float* __restrict__ X, float* __restrict__ xn)
{
    __shared__ float buf[D_IN];
    __shared__ float red[32];
    int row = blockIdx.x, tid = threadIdx.x;
    const float* segs[4] = {s0, s1, s2, s3};
    int lens[4] = {d0, d1, d2, d3};
    int off = 0;
    for (int s = 0; s < 4; s++) {
        int d = lens[s];
        if (d == 0) continue;
        const float* p = segs[s] + (size_t)row * d;
        float sum = 0.f;
        for (int i = tid; i < d; i += 256) { float v = p[i]; buf[off + i] = v; sum += v; }
        sum = blockReduceSum(sum, red);
        float mean = sum / (float)d;
        float sq = 0.f;
        for (int i = tid; i < d; i += 256) { float v = buf[off + i] - mean; sq += v * v; }
        sq = blockReduceSum(sq, red);
        float sd  = sqrtf(sq / (float)(d - 1));
        float inv = 1.f / (sd + 1e-8f);
        for (int i = tid; i < d; i += 256) buf[off + i] = (buf[off + i] - mean) * inv;
        off += d;
    }
    __syncthreads();
    float nn2 = 0.f;
    for (int i = tid; i < D_IN; i += 256) { float v = buf[i]; nn2 += v * v; }
    nn2 = blockReduceSum(nn2, red);
    float nrm = sqrtf(nn2);
    float n  = fmaxf(nrm, 1e-15f);
    float sc = tanhf(n) / n;
    float* xo = X + (size_t)row * KP1;
    for (int i = tid; i < D_IN; i += 256) xo[i] = sc * buf[i];
    for (int i = D_IN + tid; i < KP1; i += 256) xo[i] = 0.f;
    if (tid == 0) xn[row] = sc * nrm;
}

// ---------------- weight transpose+pad: W[K,N] -> Wt[N,Kp] ----------------
__global__ void transpose_pad(const float* __restrict__ W, float* __restrict__ Wt,
                              int K, int N, int Kp)
{
    __shared__ float t[32][33];
    int kb = blockIdx.x * 32, nb = blockIdx.y * 32;
    #pragma unroll
    for (int i = 0; i < 32; i += 8) {
        int kk = kb + threadIdx.y + i;
        int nn = nb + threadIdx.x;
        t[threadIdx.y + i][threadIdx.x] =
            (kk < K && nn < N) ? W[(size_t)kk * N + nn] : 0.f;
    }
    __syncthreads();
    #pragma unroll
    for (int i = 0; i < 32; i += 8) {
        int nn = nb + threadIdx.y + i;
        int kk = kb + threadIdx.x;
        if (nn < N && kk < Kp)
            Wt[(size_t)nn * Kp + kk] = t[threadIdx.x][threadIdx.y + i];
    }
}

// ---------------- fp16-split tensor GEMM, hi*hi in f32 acc, corrections in f16 acc ---
#define LDH 20
#define STG_U32 (4 * 128 * LDH)          // 10240 words per stage
#define HSMEM (2 * STG_U32 * 4)          // 81920 bytes

__device__ __forceinline__ uint32_t pack_h2(float x, float y)
{
    __half2 h = __floats2half2_rn(x, y);
    return *reinterpret_cast<uint32_t*>(&h);
}

__device__ __forceinline__ void split4(const float4 v, uint32_t& h0, uint32_t& h1,
                                       uint32_t& l0, uint32_t& l1)
{
    float ax = __half2float(__float2half_rn(v.x));
    float ay = __half2float(__float2half_rn(v.y));
    float az = __half2float(__float2half_rn(v.z));
    float aw = __half2float(__float2half_rn(v.w));
    h0 = pack_h2(ax, ay); h1 = pack_h2(az, aw);
    l0 = pack_h2(v.x - ax, v.y - ay); l1 = pack_h2(v.z - az, v.w - aw);
}

__device__ __forceinline__ void mma_f32acc(float* c, const uint32_t* a, const uint32_t* b)
{
    asm volatile(
        "mma.sync.aligned.m16n8k16.row.col.f32.f16.f16.f32 "
        "{%0,%1,%2,%3}, {%4,%5,%6,%7}, {%8,%9}, {%0,%1,%2,%3};\n"
        : "+f"(c[0]), "+f"(c[1]), "+f"(c[2]), "+f"(c[3])
        : "r"(a[0]), "r"(a[1]), "r"(a[2]), "r"(a[3]), "r"(b[0]), "r"(b[1]));
}

__device__ __forceinline__ void mma_f16acc(uint32_t* c, const uint32_t* a, const uint32_t* b)
{
    asm volatile(
        "mma.sync.aligned.m16n8k16.row.col.f16.f16.f16.f16 "
        "{%0,%1}, {%2,%3,%4,%5}, {%6,%7}, {%0,%1};\n"
        : "+r"(c[0]), "+r"(c[1])
        : "r"(a[0]), "r"(a[1]), "r"(a[2]), "r"(a[3]), "r"(b[0]), "r"(b[1]));
}

__device__ __forceinline__ void ldsm_x4(uint32_t& r0, uint32_t& r1,
                                        uint32_t& r2, uint32_t& r3, uint32_t addr)
{
    asm volatile("ldmatrix.sync.aligned.m8n8.x4.shared.b16 {%0,%1,%2,%3}, [%4];"
                 : "=r"(r0), "=r"(r1), "=r"(r2), "=r"(r3) : "r"(addr));
}

__global__ __launch_bounds__(256) void hgemm(const float* __restrict__ A,
                                             const float* __restrict__ Bt,
                                             float* __restrict__ C, int N, int K)
{
    extern __shared__ __align__(16) uint32_t hs[];
    uint32_t sb = (uint32_t)__cvta_generic_to_shared(hs);
    int tid = threadIdx.x;
    int wid = tid >> 5, lane = tid & 31;
    int g = lane >> 2, tg = lane & 3;
    int m_warp = (wid & 3) * 32;
    int n_warp = (wid >> 2) * 64;
    const float* Ab = A  + (size_t)(blockIdx.y * 128) * K;
    const float* Bb = Bt + (size_t)(blockIdx.x * 128) * K;

    // ldmatrix per-lane byte offsets (within an array, excluding stage/array base)
    uint32_t aoff[2], boff[4];
    #pragma unroll
    for (int mt = 0; mt < 2; mt++)
        aoff[mt] = (uint32_t)(((m_warp + mt * 16 + (lane & 15)) * LDH
                              + ((lane >> 4) & 1) * 4) * 4);
    #pragma unroll
    for (int p = 0; p < 4; p++)
        boff[p] = (uint32_t)(((n_warp + p * 16 + ((lane >> 4) & 1) * 8 + (lane & 7)) * LDH
                             + ((lane >> 3) & 1) * 4) * 4);

    float4 pa[4], pb[4];
    auto prefetch = [&](int k0) {
        #pragma unroll
        for (int i = 0; i < 4; i++) {
            int idx = tid + i * 256;
            int row = idx >> 3, f4 = idx & 7;
            pa[i] = *(const float4*)(Ab + (size_t)row * K + k0 + f4 * 4);
            pb[i] = *(const float4*)(Bb + (size_t)row * K + k0 + f4 * 4);
        }
    };
    auto sts = [&](int s) {
        uint32_t* Ah = hs + s * STG_U32;
        uint32_t* Al = Ah + 2560;
        uint32_t* Bh = Ah + 5120;
        uint32_t* Bl = Ah + 7680;
        #pragma unroll
        for (int i = 0; i < 4; i++) {
            int idx = tid + i * 256;
            int row = idx >> 3, f4 = idx & 7;
            int base = row * LDH + f4 * 2;
            uint32_t h0, h1, l0, l1;
            split4(pa[i], h0, h1, l0, l1);
            Ah[base] = h0; Ah[base + 1] = h1; Al[base] = l0; Al[base + 1] = l1;
            split4(pb[i], h0, h1, l0, l1);
            Bh[base] = h0; Bh[base + 1] = h1; Bl[base] = l0; Bl[base + 1] = l1;
        }
    };

    prefetch(0);
    sts(0);
    __syncthreads();

    float acc[2][8][4];
    uint32_t accC[2][8][2];
    #pragma unroll
    for (int mt = 0; mt < 2; mt++)
        #pragma unroll
        for (int nt = 0; nt < 8; nt++) {
            acc[mt][nt][0] = acc[mt][nt][1] = acc[mt][nt][2] = acc[mt][nt][3] = 0.f;
            accC[mt][nt][0] = 0u; accC[mt][nt][1] = 0u;
        }

    int nk = K / 32;
    for (int kc = 0; kc < nk; kc++) {
        int buf = kc & 1;
        bool more = (kc + 1 < nk);
        if (more) prefetch((kc + 1) * 32);
        uint32_t stage = sb + (uint32_t)(buf * STG_U32 * 4);
        #pragma unroll
        for (int ks = 0; ks < 2; ks++) {
            uint32_t ckb = (uint32_t)(ks * 32);        // 8 words = 32 bytes
            uint32_t ah[2][4], al_[2][4], bh[8][2], bl[8][2];
            #pragma unroll
            for (int mt = 0; mt < 2; mt++) {
                ldsm_x4(ah[mt][0], ah[mt][1], ah[mt][2], ah[mt][3],
                        stage + aoff[mt] + ckb);
                ldsm_x4(al_[mt][0], al_[mt][1], al_[mt][2], al_[mt][3],
                        stage + 10240u + aoff[mt] + ckb);
            }
            #pragma unroll
            for (int p = 0; p < 4; p++) {
                uint32_t r0, r1, r2, r3;
                ldsm_x4(r0, r1, r2, r3, stage + 20480u + boff[p] + ckb);
                bh[2 * p][0] = r0; bh[2 * p][1] = r1;
                bh[2 * p + 1][0] = r2; bh[2 * p + 1][1] = r3;
                ldsm_x4(r0, r1, r2, r3, stage + 30720u + boff[p] + ckb);
                bl[2 * p][0] = r0; bl[2 * p][1] = r1;
                bl[2 * p + 1][0] = r2; bl[2 * p + 1][1] = r3;
            }
            if (ks == 1 && more) sts(buf ^ 1);   // overlap STS with final MMA burst
            #pragma unroll
            for (int mt = 0; mt < 2; mt++)
                #pragma unroll
                for (int nt = 0; nt < 8; nt++) {
                    mma_f32acc(acc[mt][nt], ah[mt], bh[nt]);
                    mma_f16acc(accC[mt][nt], ah[mt], bl[nt]);
                    mma_f16acc(accC[mt][nt], al_[mt], bh[nt]);
                }
        }
        __syncthreads();
    }

    float* Cb = C + (size_t)(blockIdx.y * 128 + m_warp) * N + blockIdx.x * 128 + n_warp;
    #pragma unroll
    for (int mt = 0; mt < 2; mt++)
        #pragma unroll
        for (int nt = 0; nt < 8; nt++) {
            __half2 c0 = *reinterpret_cast<__half2*>(&accC[mt][nt][0]);
            __half2 c1 = *reinterpret_cast<__half2*>(&accC[mt][nt][1]);
            float v0 = acc[mt][nt][0] + __low2float(c0);
            float v1 = acc[mt][nt][1] + __high2float(c0);
            float v2 = acc[mt][nt][2] + __low2float(c1);
            float v3 = acc[mt][nt][3] + __high2float(c1);
            int r0 = mt * 16 + g;
            int c0i = nt * 8 + 2 * tg;
            *(float2*)&Cb[(size_t)r0 * N + c0i]       = make_float2(v0, v1);
            *(float2*)&Cb[(size_t)(r0 + 8) * N + c0i] = make_float2(v2, v3);
        }
}

// ---------------- hyperbolic epilogue: hlinear tail (+ optional mobius_tanh) ----------------
template<int N, bool DO_TANH>
__global__ void epi_kernel(const float* __restrict__ MX, const float* __restrict__ bvec,
                           const float* __restrict__ xn_in,
                           float* __restrict__ Xout, float* __restrict__ xn_out)
{
    constexpr int T = 256;
    constexpr int C = N / T;
    __shared__ float red[32];
    int row = blockIdx.x, tid = threadIdx.x;
    const float* mx = MX + (size_t)row * N;
    float m[C], b[C];
    float s_mm = 0.f, s_mb = 0.f, s_bb = 0.f;
    #pragma unroll
    for (int i = 0; i < C; i++) {
        int idx = tid + i * T;
        m[i] = mx[idx]; b[i] = bvec[idx];
        s_mm += m[i] * m[i]; s_mb += m[i] * b[i]; s_bb += b[i] * b[i];
    }
    s_mm = blockReduceSum(s_mm, red);
    s_mb = blockReduceSum(s_mb, red);
    s_bb = blockReduceSum(s_bb, red);

    float xn  = fmaxf(xn_in[row], 1e-15f);
    float mxn = fmaxf(sqrtf(s_mm), 1e-15f);
    float t   = tanhf((mxn / xn) * atanhf(fminf(xn, ATANH_LIM)));
    float tc  = fminf(t, MAXNORM);
    float s1  = tc / mxn;
    float x2 = tc * tc, xy = s1 * s_mb, y2 = s_bb;
    float den = fmaxf(1.f + 2.f * xy + x2 * y2, 1e-15f);
    float ca = (1.f + 2.f * xy + y2) * s1 / den;
    float cb = (1.f - x2) / den;
    float s_zz = 0.f;
    #pragma unroll
    for (int i = 0; i < C; i++) { m[i] = ca * m[i] + cb * b[i]; s_zz += m[i] * m[i]; }
    s_zz = blockReduceSum(s_zz, red);
    float znp = sqrtf(s_zz);
    float zn  = fmaxf(znp, 1e-15f);
    float sc  = (zn > MAXNORM) ? (MAXNORM / zn) : 1.f;
    float outn = sc * znp;
    float* xo = Xout + (size_t)row * N;
    if (!DO_TANH) {
        #pragma unroll
        for (int i = 0; i < C; i++) xo[tid + i * T] = sc * m[i];
        if (tid == 0) xn_out[row] = outn;
    } else {
        float nzn = fmaxf(outn, 1e-15f);
        float lsc = atanhf(fminf(nzn, ATANH_LIM)) / nzn * sc;
        float s_vv = 0.f;
        #pragma unroll
        for (int i = 0; i < C; i++) { m[i] = tanhf(lsc * m[i]); s_vv += m[i] * m[i]; }
        s_vv = blockReduceSum(s_vv, red);
        float vnp = sqrtf(s_vv);
        float vn  = fmaxf(vnp, 1e-15f);
        float esc = tanhf(vn) / vn;
        float en  = esc * vnp;
        float pn  = fmaxf(en, 1e-15f);
        float psc = (pn > MAXNORM) ? (MAXNORM / pn) : 1.f;
        float fsc = psc * esc;
        #pragma unroll
        for (int i = 0; i < C; i++) xo[tid + i * T] = fsc * m[i];
        if (tid == 0) xn_out[row] = fsc * vnp;
    }
}

// ---------------- mid = projx(mobius_add(0.27 (x) head, 0.73 (x) tail)) ----------------
__global__ void combine_kernel(const float* __restrict__ H, const float* __restrict__ Tl,
                               float* __restrict__ mid, float* __restrict__ midn)
{
    __shared__ float red[32];
    int row = blockIdx.x, tid = threadIdx.x;
    float h = H[(size_t)row * 256 + tid];
    float t = Tl[(size_t)row * 256 + tid];
    float shh = blockReduceSum(h * h, red);
    float stt = blockReduceSum(t * t, red);
    float sht = blockReduceSum(h * t, red);
    float hn = fmaxf(sqrtf(shh), 1e-15f);
    float tn = fmaxf(sqrtf(stt), 1e-15f);
    float th = tanhf(0.27f * atanhf(fminf(hn, ATANH_LIM)));
    float tt = tanhf(0.73f * atanhf(fminf(tn, ATANH_LIM)));
    float ah = th / hn, at = tt / tn;
    float x2 = th * th, y2 = tt * tt, xy = ah * at * sht;
    float den = fmaxf(1.f + 2.f * xy + x2 * y2, 1e-15f);
    float ca = (1.f + 2.f * xy + y2) * ah / den;
    float cb = (1.f - x2) * at / den;
    float z = ca * h + cb * t;
    float szz = blockReduceSum(z * z, red);
    float znp = sqrtf(szz);
    float zn  = fmaxf(znp, 1e-15f);
    float sc  = (zn > MAXNORM) ? (MAXNORM / zn) : 1.f;
    mid[(size_t)row * 256 + tid] = sc * z;
    if (tid == 0) midn[row] = sc * znp;
}

// ---------------- small MLP (256->64->32->2), one CTA handles 8 rows ----------------
__device__ void matvec_sm(const float* x, int K, const float* __restrict__ W, int n,
                          float* out, float* part)
{
    int tid = threadIdx.x;
    int col = tid % n;
    int q   = tid / n;
    int nch = 256 / n;
    float p = 0.f;
    for (int k = q; k < K; k += nch) p += x[k] * W[k * n + col];
    __syncthreads();
    part[tid] = p;
    __syncthreads();
    for (int s = nch / 2; s > 0; s >>= 1) {
        if (q < s) part[q * n + col] += part[(q + s) * n + col];
        __syncthreads();
    }
    if (tid < n) out[tid] = part[tid];
    __syncthreads();
}

__device__ float hlin_epi_sm(float* v, int n, const float* __restrict__ b, float xn,
                             bool do_tanh, float* red)
{
    int tid = threadIdx.x;
    float mi = (tid < n) ? v[tid] : 0.f;
    float bi = (tid < n) ? b[tid] : 0.f;
    float s_mm = blockReduceSum(mi * mi, red);
    float s_mb = blockReduceSum(mi * bi, red);
    float s_bb = blockReduceSum(bi * bi, red);
    xn = fmaxf(xn, 1e-15f);
    float mxn = fmaxf(sqrtf(s_mm), 1e-15f);
    float t  = tanhf((mxn / xn) * atanhf(fminf(xn, ATANH_LIM)));
    float tc = fminf(t, MAXNORM);
    float s1 = tc / mxn;
    float x2 = tc * tc, xy = s1 * s_mb, y2 = s_bb;
    float den = fmaxf(1.f + 2.f * xy + x2 * y2, 1e-15f);
    float ca = (1.f + 2.f * xy + y2) * s1 / den;
    float cb = (1.f - x2) / den;
    float z = ca * mi + cb * bi;
    float s_zz = blockReduceSum(z * z, red);
    float znp = sqrtf(s_zz), zn = fmaxf(znp, 1e-15f);
    float sc = (zn > MAXNORM) ? (MAXNORM / zn) : 1.f;
    float nn = sc * znp;
    if (do_tanh) {
        float nzn = fmaxf(nn, 1e-15f);
        float lsc = atanhf(fminf(nzn, ATANH_LIM)) / nzn * sc;
        float vi = tanhf(lsc * z);
        float s_vv = blockReduceSum(vi * vi, red);
        float vnp = sqrtf(s_vv), vn = fmaxf(vnp, 1e-15f);
        float esc = tanhf(vn) / vn;
        float en  = esc * vnp;
        float pn  = fmaxf(en, 1e-15f);
        float psc = (pn > MAXNORM) ? (MAXNORM / pn) : 1.f;
        if (tid < n) v[tid] = psc * esc * vi;
        nn = psc * esc * vnp;
    } else {
        if (tid < n) v[tid] = sc * z;
    }
    __syncthreads();
    return nn;
}

#define MLP_ROWS 8
__global__ void mlp_kernel(const float* __restrict__ mid, const float* __restrict__ midn,
                           const float* __restrict__ Wm1, const float* __restrict__ bm1,
                           const float* __restrict__ Wm2, const float* __restrict__ bm2,
                           const float* __restrict__ Wm3, const float* __restrict__ bm3,
                           float* __restrict__ out)
{
    __shared__ float sx[256];
    __shared__ float part[256];
    __shared__ float va[64];
    __shared__ float vb[32];
    __shared__ float vc[2];
    __shared__ float red[32];
    int tid = threadIdx.x;
    int r0 = blockIdx.x * MLP_ROWS;
    for (int r = r0; r < r0 + MLP_ROWS; r++) {
        sx[tid] = mid[(size_t)r * 256 + tid];
        float xn = midn[r];
        __syncthreads();
        matvec_sm(sx, 256, Wm1, 64, va, part);
        xn = hlin_epi_sm(va, 64, bm1, xn, true, red);
        matvec_sm(va, 64, Wm2, 32, vb, part);
        xn = hlin_epi_sm(vb, 32, bm2, xn, true, red);
        matvec_sm(vb, 32, Wm3, 2, vc, part);
        xn = hlin_epi_sm(vc, 2, bm3, xn, false, red);
        if (tid < 2) out[(size_t)r * 2 + tid] = vc[tid];
        __syncthreads();
    }
}

// ---------------- host orchestration ----------------
static void run_branch(const float* X, const float* W1t, const float* b1,
                       const float* W2t, const float* b2,
                       const float* W3t, const float* b3,
                       float* MX, float* Y, float* nrm)
{
    const int B = BATCH;
    hgemm<<<dim3(1024 / 128, B / 128), 256, HSMEM>>>(X, W1t, MX, 1024, KP1);
    epi_kernel<1024, true><<<B, 256>>>(MX, b1, nrm, Y, nrm);
    hgemm<<<dim3(512 / 128, B / 128), 256, HSMEM>>>(Y, W2t, MX, 512, 1024);
    epi_kernel<512, true><<<B, 256>>>(MX, b2, nrm, Y, nrm);
    hgemm<<<dim3(256 / 128, B / 128), 256, HSMEM>>>(Y, W3t, MX, 256, 512);
    epi_kernel<256, false><<<B, 256>>>(MX, b3, nrm, Y, nrm);
}

extern "C" void kernel_launch(void* const* d_in, const int* in_sizes, int n_in,
                              void* d_out, int out_size)
{
    const float* dcb  = (const float*)d_in[0];
    const float* dpc  = (const float*)d_in[1];
    const float* dmac = (const float*)d_in[2];
    const float* decf = (const float*)d_in[3];
    const float* tesm = (const float*)d_in[4];
    const float* tpc  = (const float*)d_in[5];
    const float* tmer = (const float*)d_in[6];
    const float* Wd1 = (const float*)d_in[7];  const float* bd1 = (const float*)d_in[8];
    const float* Wd2 = (const float*)d_in[9];  const float* bd2 = (const float*)d_in[10];
    const float* Wd3 = (const float*)d_in[11]; const float* bd3 = (const float*)d_in[12];
    const float* Wt1 = (const float*)d_in[13]; const float* bt1 = (const float*)d_in[14];
    const float* Wt2 = (const float*)d_in[15]; const float* bt2 = (const float*)d_in[16];
    const float* Wt3 = (const float*)d_in[17]; const float* bt3 = (const float*)d_in[18];
    const float* Wm1 = (const float*)d_in[19]; const float* bm1 = (const float*)d_in[20];
    const float* Wm2 = (const float*)d_in[21]; const float* bm2 = (const float*)d_in[22];
    const float* Wm3 = (const float*)d_in[23]; const float* bm3 = (const float*)d_in[24];

    float *Xd, *Xt, *MXd, *MXt, *Yd, *Yt, *nd, *nt, *mid, *nmid;
    float *Wd1t, *Wt1t, *Wd2t, *Wt2t, *Wd3t, *Wt3t;
    cudaGetSymbolAddress((void**)&Xd,   g_Xd);
    cudaGetSymbolAddress((void**)&Xt,   g_Xt);
    cudaGetSymbolAddress((void**)&MXd,  g_MXd);
    cudaGetSymbolAddress((void**)&MXt,  g_MXt);
    cudaGetSymbolAddress((void**)&Yd,   g_Yd);
    cudaGetSymbolAddress((void**)&Yt,   g_Yt);
    cudaGetSymbolAddress((void**)&nd,   g_nd);
    cudaGetSymbolAddress((void**)&nt,   g_nt);
    cudaGetSymbolAddress((void**)&mid,  g_mid);
    cudaGetSymbolAddress((void**)&nmid, g_nmid);
    cudaGetSymbolAddress((void**)&Wd1t, g_Wd1t);
    cudaGetSymbolAddress((void**)&Wt1t, g_Wt1t);
    cudaGetSymbolAddress((void**)&Wd2t, g_Wd2t);
    cudaGetSymbolAddress((void**)&Wt2t, g_Wt2t);
    cudaGetSymbolAddress((void**)&Wd3t, g_Wd3t);
    cudaGetSymbolAddress((void**)&Wt3t, g_Wt3t);

    cudaFuncSetAttribute(hgemm, cudaFuncAttributeMaxDynamicSharedMemorySize, HSMEM);

    const int B = BATCH;
    dim3 tb(32, 8);
    transpose_pad<<<dim3(KP1 / 32, 1024 / 32), tb>>>(Wd1, Wd1t, D_IN, 1024, KP1);
    transpose_pad<<<dim3(KP1 / 32, 1024 / 32), tb>>>(Wt1, Wt1t, D_IN, 1024, KP1);
    transpose_pad<<<dim3(1024 / 32, 512 / 32), tb>>>(Wd2, Wd2t, 1024, 512, 1024);
    transpose_pad<<<dim3(1024 / 32, 512 / 32), tb>>>(Wt2, Wt2t, 1024, 512, 1024);
    transpose_pad<<<dim3(512 / 32, 256 / 32), tb>>>(Wd3, Wd3t, 512, 256, 512);
    transpose_pad<<<dim3(512 / 32, 256 / 32), tb>>>(Wt3, Wt3t, 512, 256, 512);

    pre_kernel<<<B, 256>>>(dcb, 768, dpc, 11, dmac, 167, decf, 765, Xd, nd);
    pre_kernel<<<B, 256>>>(tesm, 1280, tpc, 11, tmer, 420, nullptr, 0, Xt, nt);

    run_branch(Xd, Wd1t, bd1, Wd2t, bd2, Wd3t, bd3, MXd, Yd, nd);
    run_branch(Xt, Wt1t, bt1, Wt2t, bt2, Wt3t, bt3, MXt, Yt, nt);

    combine_kernel<<<B, 256>>>(Yd, Yt, mid, nmid);

    mlp_kernel<<<B / MLP_ROWS, 256>>>(mid, nmid, Wm1, bm1, Wm2, bm2, Wm3, bm3,
                                      (float*)d_out);
}

// round 16
// speedup vs baseline: 1.0908x; 1.0908x over previous
#include <cuda_runtime.h>
#include <cuda_fp16.h>
#include <math.h>
#include <stdint.h>

#define BATCH 16384
#define D_IN  1711
#define KP1   1728                  // K padded to multiple of 32
#define ATANH_LIM (1.0f - 1e-5f)
#define MAXNORM   (1.0f - 4e-3f)

// ---------------- scratch (static device globals; no allocation) ----------------
__device__ float g_Xd[BATCH * KP1];
__device__ float g_Xt[BATCH * KP1];
__device__ float g_Wd1t[1024 * KP1];
__device__ float g_Wt1t[1024 * KP1];
__device__ float g_Wd2t[512 * 1024];
__device__ float g_Wt2t[512 * 1024];
__device__ float g_Wd3t[256 * 512];
__device__ float g_Wt3t[256 * 512];
__device__ float g_MXd[BATCH * 1024];
__device__ float g_MXt[BATCH * 1024];
__device__ float g_Yd[BATCH * 1024];
__device__ float g_Yt[BATCH * 1024];
__device__ float g_nd[BATCH];
__device__ float g_nt[BATCH];
__device__ float g_mid[BATCH * 256];
__device__ float g_nmid[BATCH];

// ---------------- block reductions (256 threads) ----------------
__device__ __forceinline__ float blockReduceSum(float v, float* red)
{
    int lane = threadIdx.x & 31;
    int w    = threadIdx.x >> 5;
    #pragma unroll
    for (int o = 16; o > 0; o >>= 1) v += __shfl_xor_sync(0xffffffffu, v, o);
    __syncthreads();                 // protect red from previous call's readers
    if (lane == 0) red[w] = v;
    __syncthreads();
    float s = 0.f;
    #pragma unroll
    for (int i = 0; i < 8; i++) s += red[i];
    return s;
}

__device__ __forceinline__ void blockReduce2(float& a, float& b, float* red)
{
    int lane = threadIdx.x & 31;
    int w    = threadIdx.x >> 5;
    #pragma unroll
    for (int o = 16; o > 0; o >>= 1) {
        a += __shfl_xor_sync(0xffffffffu, a, o);
        b += __shfl_xor_sync(0xffffffffu, b, o);
    }
    __syncthreads();
    if (lane == 0) { red[w] = a; red[8 + w] = b; }
    __syncthreads();
    a = 0.f; b = 0.f;
    #pragma unroll
    for (int i = 0; i < 8; i++) { a += red[i]; b += red[8 + i]; }
}

// ---------------- preprocess: per-row zscore(segments) + concat + expmap0 ----------------
// One-pass mean/var per segment; row norm computed analytically from segment stats.
__global__ void pre_kernel(const float* __restrict__ s0, int d0,
                           const float* __restrict__ s1, int d1,
                           const float* __restrict__ s2, int d2,
                           const float* __restrict__ s3, int d3,
                           float* __restrict__ X, float* __restrict__ xn)
{
    __shared__ float buf[D_IN];
    __shared__ float red[16];
    int row = blockIdx.x, tid = threadIdx.x;
    const float* segs[4] = {s0, s1, s2, s3};
    int lens[4] = {d0, d1, d2, d3};
    float ms[4], is[4];
    float nn2 = 0.f;
    int off = 0;
    for (int s = 0; s < 4; s++) {
        int d = lens[s];
        if (d == 0) { ms[s] = 0.f; is[s] = 0.f; continue; }
        const float* p = segs[s] + (size_t)row * d;
        float sum = 0.f, sq = 0.f;
        for (int i = tid; i < d; i += 256) {
            float v = p[i]; buf[off + i] = v; sum += v; sq += v * v;
        }
        blockReduce2(sum, sq, red);
        float mean = sum / (float)d;
        float ssd  = fmaxf(sq - sum * mean, 0.f);          // (d-1)*var
        float sd   = sqrtf(ssd / (float)(d - 1));          // ddof=1
        float inv  = 1.f / (sd + 1e-8f);
        ms[s] = mean; is[s] = inv;
        nn2 += ssd * inv * inv;                             // ||zscore(seg)||^2
        off += d;
    }
    float nrm = sqrtf(nn2);
    float n  = fmaxf(nrm, 1e-15f);
    float sc = tanhf(n) / n;                               // expmap0
    float* xo = X + (size_t)row * KP1;
    off = 0;
    for (int s = 0; s < 4; s++) {
        int d = lens[s];
        if (d == 0) continue;
        float a = is[s] * sc, m0 = ms[s];
        for (int i = tid; i < d; i += 256)
            xo[off + i] = (buf[off + i] - m0) * a;
        off += d;
    }
    for (int i = D_IN + tid; i < KP1; i += 256) xo[i] = 0.f;
    if (tid == 0) xn[row] = sc * nrm;
}

// ---------------- weight transpose+pad: W[K,N] -> Wt[N,Kp] ----------------
__global__ void transpose_pad(const float* __restrict__ W, float* __restrict__ Wt,
                              int K, int N, int Kp)
{
    __shared__ float t[32][33];
    int kb = blockIdx.x * 32, nb = blockIdx.y * 32;
    #pragma unroll
    for (int i = 0; i < 32; i += 8) {
        int kk = kb + threadIdx.y + i;
        int nn = nb + threadIdx.x;
        t[threadIdx.y + i][threadIdx.x] =
            (kk < K && nn < N) ? W[(size_t)kk * N + nn] : 0.f;
    }
    __syncthreads();
    #pragma unroll
    for (int i = 0; i < 32; i += 8) {
        int nn = nb + threadIdx.y + i;
        int kk = kb + threadIdx.x;
        if (nn < N && kk < Kp)
            Wt[(size_t)nn * Kp + kk] = t[threadIdx.x][threadIdx.y + i];
    }
}

// ---------------- 3xfp16-split tensor GEMM (R9-proven): C = A @ Bt^T ----------------
#define LDH 20
#define STG_U32 (4 * 128 * LDH)
#define HSMEM (2 * STG_U32 * 4)

__device__ __forceinline__ uint32_t pack_h2(float x, float y)
{
    __half2 h = __floats2half2_rn(x, y);
    return *reinterpret_cast<uint32_t*>(&h);
}

__device__ __forceinline__ void split4(const float4 v, uint32_t& h0, uint32_t& h1,
                                       uint32_t& l0, uint32_t& l1)
{
    float ax = __half2float(__float2half_rn(v.x));
    float ay = __half2float(__float2half_rn(v.y));
    float az = __half2float(__float2half_rn(v.z));
    float aw = __half2float(__float2half_rn(v.w));
    h0 = pack_h2(ax, ay); h1 = pack_h2(az, aw);
    l0 = pack_h2(v.x - ax, v.y - ay); l1 = pack_h2(v.z - az, v.w - aw);
}

__device__ __forceinline__ void mma_f16(float* c, const uint32_t* a, const uint32_t* b)
{
    asm volatile(
        "mma.sync.aligned.m16n8k16.row.col.f32.f16.f16.f32 "
        "{%0,%1,%2,%3}, {%4,%5,%6,%7}, {%8,%9}, {%0,%1,%2,%3};\n"
        : "+f"(c[0]), "+f"(c[1]), "+f"(c[2]), "+f"(c[3])
        : "r"(a[0]), "r"(a[1]), "r"(a[2]), "r"(a[3]), "r"(b[0]), "r"(b[1]));
}

__global__ __launch_bounds__(256) void hgemm(const float* __restrict__ A,
                                             const float* __restrict__ Bt,
                                             float* __restrict__ C, int N, int K)
{
    extern __shared__ __align__(16) uint32_t hs[];
    int tid = threadIdx.x;
    int wid = tid >> 5, lane = tid & 31;
    int g = lane >> 2, tg = lane & 3;
    int m_warp = (wid & 3) * 32;
    int n_warp = (wid >> 2) * 64;
    const float* Ab = A  + (size_t)(blockIdx.y * 128) * K;
    const float* Bb = Bt + (size_t)(blockIdx.x * 128) * K;

    float4 pa[4], pb[4];
    auto prefetch = [&](int k0) {
        #pragma unroll
        for (int i = 0; i < 4; i++) {
            int idx = tid + i * 256;
            int row = idx >> 3, f4 = idx & 7;
            pa[i] = *(const float4*)(Ab + (size_t)row * K + k0 + f4 * 4);
            pb[i] = *(const float4*)(Bb + (size_t)row * K + k0 + f4 * 4);
        }
    };
    auto sts = [&](int s) {
        uint32_t* Ah = hs + s * STG_U32;
        uint32_t* Al = Ah + 2560;
        uint32_t* Bh = Ah + 5120;
        uint32_t* Bl = Ah + 7680;
        #pragma unroll
        for (int i = 0; i < 4; i++) {
            int idx = tid + i * 256;
            int row = idx >> 3, f4 = idx & 7;
            int base = row * LDH + f4 * 2;
            uint32_t h0, h1, l0, l1;
            split4(pa[i], h0, h1, l0, l1);
            Ah[base] = h0; Ah[base + 1] = h1; Al[base] = l0; Al[base + 1] = l1;
            split4(pb[i], h0, h1, l0, l1);
            Bh[base] = h0; Bh[base + 1] = h1; Bl[base] = l0; Bl[base + 1] = l1;
        }
    };

    prefetch(0);
    sts(0);
    __syncthreads();

    float acc[2][8][4];
    #pragma unroll
    for (int mt = 0; mt < 2; mt++)
        #pragma unroll
        for (int nt = 0; nt < 8; nt++)
            #pragma unroll
            for (int i = 0; i < 4; i++) acc[mt][nt][i] = 0.f;

    int nk = K / 32;
    for (int kc = 0; kc < nk; kc++) {
        int buf = kc & 1;
        bool more = (kc + 1 < nk);
        if (more) prefetch((kc + 1) * 32);
        const uint32_t* Ah = hs + buf * STG_U32;
        const uint32_t* Al = Ah + 2560;
        const uint32_t* Bh = Ah + 5120;
        const uint32_t* Bl = Ah + 7680;
        #pragma unroll
        for (int ks = 0; ks < 2; ks++) {
            int ck = ks * 8;
            uint32_t ah[2][4], al_[2][4], bh[8][2], bl[8][2];
            #pragma unroll
            for (int mt = 0; mt < 2; mt++) {
                int mb = m_warp + mt * 16;
                int r0 = (mb + g) * LDH, r1 = (mb + 8 + g) * LDH;
                ah[mt][0] = Ah[r0 + ck + tg];     ah[mt][1] = Ah[r1 + ck + tg];
                ah[mt][2] = Ah[r0 + ck + tg + 4]; ah[mt][3] = Ah[r1 + ck + tg + 4];
                al_[mt][0] = Al[r0 + ck + tg];     al_[mt][1] = Al[r1 + ck + tg];
                al_[mt][2] = Al[r0 + ck + tg + 4]; al_[mt][3] = Al[r1 + ck + tg + 4];
            }
            #pragma unroll
            for (int nt = 0; nt < 8; nt++) {
                int rb = (n_warp + nt * 8 + g) * LDH;
                bh[nt][0] = Bh[rb + ck + tg]; bh[nt][1] = Bh[rb + ck + tg + 4];
                bl[nt][0] = Bl[rb + ck + tg]; bl[nt][1] = Bl[rb + ck + tg + 4];
            }
            if (ks == 1 && more) sts(buf ^ 1);
            #pragma unroll
            for (int mt = 0; mt < 2; mt++)
                #pragma unroll
                for (int nt = 0; nt < 8; nt++) {
                    mma_f16(acc[mt][nt], ah[mt], bh[nt]);
                    mma_f16(acc[mt][nt], ah[mt], bl[nt]);
                    mma_f16(acc[mt][nt], al_[mt], bh[nt]);
                }
        }
        __syncthreads();
    }

    float* Cb = C + (size_t)(blockIdx.y * 128 + m_warp) * N + blockIdx.x * 128 + n_warp;
    #pragma unroll
    for (int mt = 0; mt < 2; mt++)
        #pragma unroll
        for (int nt = 0; nt < 8; nt++) {
            int r0 = mt * 16 + g;
            int c0 = nt * 8 + 2 * tg;
            *(float2*)&Cb[(size_t)r0 * N + c0]       = make_float2(acc[mt][nt][0], acc[mt][nt][1]);
            *(float2*)&Cb[(size_t)(r0 + 8) * N + c0] = make_float2(acc[mt][nt][2], acc[mt][nt][3]);
        }
}

// ---------------- hyperbolic epilogue: hlinear tail (+ optional mobius_tanh) ----------------
template<int N, bool DO_TANH>
__global__ void epi_kernel(const float* __restrict__ MX, const float* __restrict__ bvec,
                           const float* __restrict__ xn_in,
                           float* __restrict__ Xout, float* __restrict__ xn_out)
{
    constexpr int T = 256;
    constexpr int C = N / T;
    __shared__ float red[32];
    int row = blockIdx.x, tid = threadIdx.x;
    const float* mx = MX + (size_t)row * N;
    float m[C], b[C];
    float s_mm = 0.f, s_mb = 0.f, s_bb = 0.f;
    #pragma unroll
    for (int i = 0; i < C; i++) {
        int idx = tid + i * T;
        m[i] = mx[idx]; b[i] = bvec[idx];
        s_mm += m[i] * m[i]; s_mb += m[i] * b[i]; s_bb += b[i] * b[i];
    }
    s_mm = blockReduceSum(s_mm, red);
    s_mb = blockReduceSum(s_mb, red);
    s_bb = blockReduceSum(s_bb, red);

    float xn  = fmaxf(xn_in[row], 1e-15f);
    float mxn = fmaxf(sqrtf(s_mm), 1e-15f);
    float t   = tanhf((mxn / xn) * atanhf(fminf(xn, ATANH_LIM)));
    float tc  = fminf(t, MAXNORM);
    float s1  = tc / mxn;
    float x2 = tc * tc, xy = s1 * s_mb, y2 = s_bb;
    float den = fmaxf(1.f + 2.f * xy + x2 * y2, 1e-15f);
    float ca = (1.f + 2.f * xy + y2) * s1 / den;
    float cb = (1.f - x2) / den;
    float s_zz = 0.f;
    #pragma unroll
    for (int i = 0; i < C; i++) { m[i] = ca * m[i] + cb * b[i]; s_zz += m[i] * m[i]; }
    s_zz = blockReduceSum(s_zz, red);
    float znp = sqrtf(s_zz);
    float zn  = fmaxf(znp, 1e-15f);
    float sc  = (zn > MAXNORM) ? (MAXNORM / zn) : 1.f;
    float outn = sc * znp;
    float* xo = Xout + (size_t)row * N;
    if (!DO_TANH) {
        #pragma unroll
        for (int i = 0; i < C; i++) xo[tid + i * T] = sc * m[i];
        if (tid == 0) xn_out[row] = outn;
    } else {
        float nzn = fmaxf(outn, 1e-15f);
        float lsc = atanhf(fminf(nzn, ATANH_LIM)) / nzn * sc;
        float s_vv = 0.f;
        #pragma unroll
        for (int i = 0; i < C; i++) { m[i] = tanhf(lsc * m[i]); s_vv += m[i] * m[i]; }
        s_vv = blockReduceSum(s_vv, red);
        float vnp = sqrtf(s_vv);
        float vn  = fmaxf(vnp, 1e-15f);
        float esc = tanhf(vn) / vn;
        float en  = esc * vnp;
        float pn  = fmaxf(en, 1e-15f);
        float psc = (pn > MAXNORM) ? (MAXNORM / pn) : 1.f;
        float fsc = psc * esc;
        #pragma unroll
        for (int i = 0; i < C; i++) xo[tid + i * T] = fsc * m[i];
        if (tid == 0) xn_out[row] = fsc * vnp;
    }
}

// ---------------- mid = projx(mobius_add(0.27 (x) head, 0.73 (x) tail)) ----------------
__global__ void combine_kernel(const float* __restrict__ H, const float* __restrict__ Tl,
                               float* __restrict__ mid, float* __restrict__ midn)
{
    __shared__ float red[32];
    int row = blockIdx.x, tid = threadIdx.x;
    float h = H[(size_t)row * 256 + tid];
    float t = Tl[(size_t)row * 256 + tid];
    float shh = blockReduceSum(h * h, red);
    float stt = blockReduceSum(t * t, red);
    float sht = blockReduceSum(h * t, red);
    float hn = fmaxf(sqrtf(shh), 1e-15f);
    float tn = fmaxf(sqrtf(stt), 1e-15f);
    float th = tanhf(0.27f * atanhf(fminf(hn, ATANH_LIM)));
    float tt = tanhf(0.73f * atanhf(fminf(tn, ATANH_LIM)));
    float ah = th / hn, at = tt / tn;
    float x2 = th * th, y2 = tt * tt, xy = ah * at * sht;
    float den = fmaxf(1.f + 2.f * xy + x2 * y2, 1e-15f);
    float ca = (1.f + 2.f * xy + y2) * ah / den;
    float cb = (1.f - x2) * at / den;
    float z = ca * h + cb * t;
    float szz = blockReduceSum(z * z, red);
    float znp = sqrtf(szz);
    float zn  = fmaxf(znp, 1e-15f);
    float sc  = (zn > MAXNORM) ? (MAXNORM / zn) : 1.f;
    mid[(size_t)row * 256 + tid] = sc * z;
    if (tid == 0) midn[row] = sc * znp;
}

// ---------------- small MLP (256->64->32->2), one CTA handles 8 rows ----------------
__device__ void matvec_sm(const float* x, int K, const float* __restrict__ W, int n,
                          float* out, float* part)
{
    int tid = threadIdx.x;
    int col = tid % n;
    int q   = tid / n;
    int nch = 256 / n;
    float p = 0.f;
    for (int k = q; k < K; k += nch) p += x[k] * W[k * n + col];
    __syncthreads();
    part[tid] = p;
    __syncthreads();
    for (int s = nch / 2; s > 0; s >>= 1) {
        if (q < s) part[q * n + col] += part[(q + s) * n + col];
        __syncthreads();
    }
    if (tid < n) out[tid] = part[tid];
    __syncthreads();
}

__device__ float hlin_epi_sm(float* v, int n, const float* __restrict__ b, float xn,
                             bool do_tanh, float* red)
{
    int tid = threadIdx.x;
    float mi = (tid < n) ? v[tid] : 0.f;
    float bi = (tid < n) ? b[tid] : 0.f;
    float s_mm = blockReduceSum(mi * mi, red);
    float s_mb = blockReduceSum(mi * bi, red);
    float s_bb = blockReduceSum(bi * bi, red);
    xn = fmaxf(xn, 1e-15f);
    float mxn = fmaxf(sqrtf(s_mm), 1e-15f);
    float t  = tanhf((mxn / xn) * atanhf(fminf(xn, ATANH_LIM)));
    float tc = fminf(t, MAXNORM);
    float s1 = tc / mxn;
    float x2 = tc * tc, xy = s1 * s_mb, y2 = s_bb;
    float den = fmaxf(1.f + 2.f * xy + x2 * y2, 1e-15f);
    float ca = (1.f + 2.f * xy + y2) * s1 / den;
    float cb = (1.f - x2) / den;
    float z = ca * mi + cb * bi;
    float s_zz = blockReduceSum(z * z, red);
    float znp = sqrtf(s_zz), zn = fmaxf(znp, 1e-15f);
    float sc = (zn > MAXNORM) ? (MAXNORM / zn) : 1.f;
    float nn = sc * znp;
    if (do_tanh) {
        float nzn = fmaxf(nn, 1e-15f);
        float lsc = atanhf(fminf(nzn, ATANH_LIM)) / nzn * sc;
        float vi = tanhf(lsc * z);
        float s_vv = blockReduceSum(vi * vi, red);
        float vnp = sqrtf(s_vv), vn = fmaxf(vnp, 1e-15f);
        float esc = tanhf(vn) / vn;
        float en  = esc * vnp;
        float pn  = fmaxf(en, 1e-15f);
        float psc = (pn > MAXNORM) ? (MAXNORM / pn) : 1.f;
        if (tid < n) v[tid] = psc * esc * vi;
        nn = psc * esc * vnp;
    } else {
        if (tid < n) v[tid] = sc * z;
    }
    __syncthreads();
    return nn;
}

#define MLP_ROWS 8
__global__ void mlp_kernel(const float* __restrict__ mid, const float* __restrict__ midn,
                           const float* __restrict__ Wm1, const float* __restrict__ bm1,
                           const float* __restrict__ Wm2, const float* __restrict__ bm2,
                           const float* __restrict__ Wm3, const float* __restrict__ bm3,
                           float* __restrict__ out)
{
    __shared__ float sx[256];
    __shared__ float part[256];
    __shared__ float va[64];
    __shared__ float vb[32];
    __shared__ float vc[2];
    __shared__ float red[32];
    int tid = threadIdx.x;
    int r0 = blockIdx.x * MLP_ROWS;
    for (int r = r0; r < r0 + MLP_ROWS; r++) {
        sx[tid] = mid[(size_t)r * 256 + tid];
        float xn = midn[r];
        __syncthreads();
        matvec_sm(sx, 256, Wm1, 64, va, part);
        xn = hlin_epi_sm(va, 64, bm1, xn, true, red);
        matvec_sm(va, 64, Wm2, 32, vb, part);
        xn = hlin_epi_sm(vb, 32, bm2, xn, true, red);
        matvec_sm(vb, 32, Wm3, 2, vc, part);
        xn = hlin_epi_sm(vc, 2, bm3, xn, false, red);
        if (tid < 2) out[(size_t)r * 2 + tid] = vc[tid];
        __syncthreads();
    }
}

// ---------------- host orchestration ----------------
static void run_branch(const float* X, const float* W1t, const float* b1,
                       const float* W2t, const float* b2,
                       const float* W3t, const float* b3,
                       float* MX, float* Y, float* nrm)
{
    const int B = BATCH;
    hgemm<<<dim3(1024 / 128, B / 128), 256, HSMEM>>>(X, W1t, MX, 1024, KP1);
    epi_kernel<1024, true><<<B, 256>>>(MX, b1, nrm, Y, nrm);
    hgemm<<<dim3(512 / 128, B / 128), 256, HSMEM>>>(Y, W2t, MX, 512, 1024);
    epi_kernel<512, true><<<B, 256>>>(MX, b2, nrm, Y, nrm);
    hgemm<<<dim3(256 / 128, B / 128), 256, HSMEM>>>(Y, W3t, MX, 256, 512);
    epi_kernel<256, false><<<B, 256>>>(MX, b3, nrm, Y, nrm);
}

extern "C" void kernel_launch(void* const* d_in, const int* in_sizes, int n_in,
                              void* d_out, int out_size)
{
    const float* dcb  = (const float*)d_in[0];
    const float* dpc  = (const float*)d_in[1];
    const float* dmac = (const float*)d_in[2];
    const float* decf = (const float*)d_in[3];
    const float* tesm = (const float*)d_in[4];
    const float* tpc  = (const float*)d_in[5];
    const float* tmer = (const float*)d_in[6];
    const float* Wd1 = (const float*)d_in[7];  const float* bd1 = (const float*)d_in[8];
    const float* Wd2 = (const float*)d_in[9];  const float* bd2 = (const float*)d_in[10];
    const float* Wd3 = (const float*)d_in[11]; const float* bd3 = (const float*)d_in[12];
    const float* Wt1 = (const float*)d_in[13]; const float* bt1 = (const float*)d_in[14];
    const float* Wt2 = (const float*)d_in[15]; const float* bt2 = (const float*)d_in[16];
    const float* Wt3 = (const float*)d_in[17]; const float* bt3 = (const float*)d_in[18];
    const float* Wm1 = (const float*)d_in[19]; const float* bm1 = (const float*)d_in[20];
    const float* Wm2 = (const float*)d_in[21]; const float* bm2 = (const float*)d_in[22];
    const float* Wm3 = (const float*)d_in[23]; const float* bm3 = (const float*)d_in[24];

    float *Xd, *Xt, *MXd, *MXt, *Yd, *Yt, *nd, *nt, *mid, *nmid;
    float *Wd1t, *Wt1t, *Wd2t, *Wt2t, *Wd3t, *Wt3t;
    cudaGetSymbolAddress((void**)&Xd,   g_Xd);
    cudaGetSymbolAddress((void**)&Xt,   g_Xt);
    cudaGetSymbolAddress((void**)&MXd,  g_MXd);
    cudaGetSymbolAddress((void**)&MXt,  g_MXt);
    cudaGetSymbolAddress((void**)&Yd,   g_Yd);
    cudaGetSymbolAddress((void**)&Yt,   g_Yt);
    cudaGetSymbolAddress((void**)&nd,   g_nd);
    cudaGetSymbolAddress((void**)&nt,   g_nt);
    cudaGetSymbolAddress((void**)&mid,  g_mid);
    cudaGetSymbolAddress((void**)&nmid, g_nmid);
    cudaGetSymbolAddress((void**)&Wd1t, g_Wd1t);
    cudaGetSymbolAddress((void**)&Wt1t, g_Wt1t);
    cudaGetSymbolAddress((void**)&Wd2t, g_Wd2t);
    cudaGetSymbolAddress((void**)&Wt2t, g_Wt2t);
    cudaGetSymbolAddress((void**)&Wd3t, g_Wd3t);
    cudaGetSymbolAddress((void**)&Wt3t, g_Wt3t);

    cudaFuncSetAttribute(hgemm, cudaFuncAttributeMaxDynamicSharedMemorySize, HSMEM);

    const int B = BATCH;
    dim3 tb(32, 8);
    transpose_pad<<<dim3(KP1 / 32, 1024 / 32), tb>>>(Wd1, Wd1t, D_IN, 1024, KP1);
    transpose_pad<<<dim3(KP1 / 32, 1024 / 32), tb>>>(Wt1, Wt1t, D_IN, 1024, KP1);
    transpose_pad<<<dim3(1024 / 32, 512 / 32), tb>>>(Wd2, Wd2t, 1024, 512, 1024);
    transpose_pad<<<dim3(1024 / 32, 512 / 32), tb>>>(Wt2, Wt2t, 1024, 512, 1024);
    transpose_pad<<<dim3(512 / 32, 256 / 32), tb>>>(Wd3, Wd3t, 512, 256, 512);
    transpose_pad<<<dim3(512 / 32, 256 / 32), tb>>>(Wt3, Wt3t, 512, 256, 512);

    pre_kernel<<<B, 256>>>(dcb, 768, dpc, 11, dmac, 167, decf, 765, Xd, nd);
    pre_kernel<<<B, 256>>>(tesm, 1280, tpc, 11, tmer, 420, nullptr, 0, Xt, nt);

    run_branch(Xd, Wd1t, bd1, Wd2t, bd2, Wd3t, bd3, MXd, Yd, nd);
    run_branch(Xt, Wt1t, bt1, Wt2t, bt2, Wt3t, bt3, MXt, Yt, nt);

    combine_kernel<<<B, 256>>>(Yd, Yt, mid, nmid);

    mlp_kernel<<<B / MLP_ROWS, 256>>>(mid, nmid, Wm1, bm1, Wm2, bm2, Wm3, bm3,
                                      (float*)d_out);
}

// round 17
// speedup vs baseline: 1.0944x; 1.0033x over previous
#include <cuda_runtime.h>
#include <cuda_fp16.h>
#include <math.h>
#include <stdint.h>

#define BATCH 16384
#define D_IN  1711
#define KP1   1728                  // K padded to multiple of 32
#define ATANH_LIM (1.0f - 1e-5f)
#define MAXNORM   (1.0f - 4e-3f)

// ---------------- scratch (static device globals; no allocation) ----------------
__device__ float g_Xd[BATCH * KP1];
__device__ float g_Xt[BATCH * KP1];
__device__ float g_Wd1t[1024 * KP1];
__device__ float g_Wt1t[1024 * KP1];
__device__ float g_Wd2t[512 * 1024];
__device__ float g_Wt2t[512 * 1024];
__device__ float g_Wd3t[256 * 512];
__device__ float g_Wt3t[256 * 512];
__device__ float g_MXd[BATCH * 1024];
__device__ float g_MXt[BATCH * 1024];
__device__ float g_Yd[BATCH * 1024];
__device__ float g_Yt[BATCH * 1024];
__device__ float g_nd[BATCH];
__device__ float g_nt[BATCH];
__device__ float g_mid[BATCH * 256];
__device__ float g_nmid[BATCH];

// ---------------- block reductions (256 threads) ----------------
__device__ __forceinline__ float blockReduceSum(float v, float* red)
{
    int lane = threadIdx.x & 31;
    int w    = threadIdx.x >> 5;
    #pragma unroll
    for (int o = 16; o > 0; o >>= 1) v += __shfl_xor_sync(0xffffffffu, v, o);
    __syncthreads();                 // protect red from previous call's readers
    if (lane == 0) red[w] = v;
    __syncthreads();
    float s = 0.f;
    #pragma unroll
    for (int i = 0; i < 8; i++) s += red[i];
    return s;
}

// fused 3-value reduction: one shuffle round + one shared round
__device__ __forceinline__ void blockReduce3(float& a, float& b, float& c, float* red)
{
    int lane = threadIdx.x & 31;
    int w    = threadIdx.x >> 5;
    #pragma unroll
    for (int o = 16; o > 0; o >>= 1) {
        a += __shfl_xor_sync(0xffffffffu, a, o);
        b += __shfl_xor_sync(0xffffffffu, b, o);
        c += __shfl_xor_sync(0xffffffffu, c, o);
    }
    __syncthreads();
    if (lane == 0) { red[w] = a; red[8 + w] = b; red[16 + w] = c; }
    __syncthreads();
    a = 0.f; b = 0.f; c = 0.f;
    #pragma unroll
    for (int i = 0; i < 8; i++) { a += red[i]; b += red[8 + i]; c += red[16 + i]; }
}

__device__ __forceinline__ void blockReduce2(float& a, float& b, float* red)
{
    int lane = threadIdx.x & 31;
    int w    = threadIdx.x >> 5;
    #pragma unroll
    for (int o = 16; o > 0; o >>= 1) {
        a += __shfl_xor_sync(0xffffffffu, a, o);
        b += __shfl_xor_sync(0xffffffffu, b, o);
    }
    __syncthreads();
    if (lane == 0) { red[w] = a; red[8 + w] = b; }
    __syncthreads();
    a = 0.f; b = 0.f;
    #pragma unroll
    for (int i = 0; i < 8; i++) { a += red[i]; b += red[8 + i]; }
}

// ---------------- preprocess: per-row zscore(segments) + concat + expmap0 ----------------
// One-pass mean/var per segment; row norm computed analytically from segment stats.
__global__ void pre_kernel(const float* __restrict__ s0, int d0,
                           const float* __restrict__ s1, int d1,
                           const float* __restrict__ s2, int d2,
                           const float* __restrict__ s3, int d3,
                           float* __restrict__ X, float* __restrict__ xn)
{
    __shared__ float buf[D_IN];
    __shared__ float red[24];
    int row = blockIdx.x, tid = threadIdx.x;
    const float* segs[4] = {s0, s1, s2, s3};
    int lens[4] = {d0, d1, d2, d3};
    float ms[4], is[4];
    float nn2 = 0.f;
    int off = 0;
    for (int s = 0; s < 4; s++) {
        int d = lens[s];
        if (d == 0) { ms[s] = 0.f; is[s] = 0.f; continue; }
        const float* p = segs[s] + (size_t)row * d;
        float sum = 0.f, sq = 0.f;
        for (int i = tid; i < d; i += 256) {
            float v = p[i]; buf[off + i] = v; sum += v; sq += v * v;
        }
        blockReduce2(sum, sq, red);
        float mean = sum / (float)d;
        float ssd  = fmaxf(sq - sum * mean, 0.f);          // (d-1)*var
        float sd   = sqrtf(ssd / (float)(d - 1));          // ddof=1
        float inv  = 1.f / (sd + 1e-8f);
        ms[s] = mean; is[s] = inv;
        nn2 += ssd * inv * inv;                             // ||zscore(seg)||^2
        off += d;
    }
    float nrm = sqrtf(nn2);
    float n  = fmaxf(nrm, 1e-15f);
    float sc = tanhf(n) / n;                               // expmap0
    float* xo = X + (size_t)row * KP1;
    off = 0;
    for (int s = 0; s < 4; s++) {
        int d = lens[s];
        if (d == 0) continue;
        float a = is[s] * sc, m0 = ms[s];
        for (int i = tid; i < d; i += 256)
            xo[off + i] = (buf[off + i] - m0) * a;
        off += d;
    }
    for (int i = D_IN + tid; i < KP1; i += 256) xo[i] = 0.f;
    if (tid == 0) xn[row] = sc * nrm;
}

// ---------------- weight transpose+pad: W[K,N] -> Wt[N,Kp] ----------------
__global__ void transpose_pad(const float* __restrict__ W, float* __restrict__ Wt,
                              int K, int N, int Kp)
{
    __shared__ float t[32][33];
    int kb = blockIdx.x * 32, nb = blockIdx.y * 32;
    #pragma unroll
    for (int i = 0; i < 32; i += 8) {
        int kk = kb + threadIdx.y + i;
        int nn = nb + threadIdx.x;
        t[threadIdx.y + i][threadIdx.x] =
            (kk < K && nn < N) ? W[(size_t)kk * N + nn] : 0.f;
    }
    __syncthreads();
    #pragma unroll
    for (int i = 0; i < 32; i += 8) {
        int nn = nb + threadIdx.y + i;
        int kk = kb + threadIdx.x;
        if (nn < N && kk < Kp)
            Wt[(size_t)nn * Kp + kk] = t[threadIdx.x][threadIdx.y + i];
    }
}

// ---------------- 3xfp16-split tensor GEMM (R9-proven): C = A @ Bt^T ----------------
#define LDH 20
#define STG_U32 (4 * 128 * LDH)
#define HSMEM (2 * STG_U32 * 4)

__device__ __forceinline__ uint32_t pack_h2(float x, float y)
{
    __half2 h = __floats2half2_rn(x, y);
    return *reinterpret_cast<uint32_t*>(&h);
}

__device__ __forceinline__ void split4(const float4 v, uint32_t& h0, uint32_t& h1,
                                       uint32_t& l0, uint32_t& l1)
{
    float ax = __half2float(__float2half_rn(v.x));
    float ay = __half2float(__float2half_rn(v.y));
    float az = __half2float(__float2half_rn(v.z));
    float aw = __half2float(__float2half_rn(v.w));
    h0 = pack_h2(ax, ay); h1 = pack_h2(az, aw);
    l0 = pack_h2(v.x - ax, v.y - ay); l1 = pack_h2(v.z - az, v.w - aw);
}

__device__ __forceinline__ void mma_f16(float* c, const uint32_t* a, const uint32_t* b)
{
    asm volatile(
        "mma.sync.aligned.m16n8k16.row.col.f32.f16.f16.f32 "
        "{%0,%1,%2,%3}, {%4,%5,%6,%7}, {%8,%9}, {%0,%1,%2,%3};\n"
        : "+f"(c[0]), "+f"(c[1]), "+f"(c[2]), "+f"(c[3])
        : "r"(a[0]), "r"(a[1]), "r"(a[2]), "r"(a[3]), "r"(b[0]), "r"(b[1]));
}

__global__ __launch_bounds__(256) void hgemm(const float* __restrict__ A,
                                             const float* __restrict__ Bt,
                                             float* __restrict__ C, int N, int K)
{
    extern __shared__ __align__(16) uint32_t hs[];
    int tid = threadIdx.x;
    int wid = tid >> 5, lane = tid & 31;
    int g = lane >> 2, tg = lane & 3;
    int m_warp = (wid & 3) * 32;
    int n_warp = (wid >> 2) * 64;
    const float* Ab = A  + (size_t)(blockIdx.y * 128) * K;
    const float* Bb = Bt + (size_t)(blockIdx.x * 128) * K;

    float4 pa[4], pb[4];
    auto prefetch = [&](int k0) {
        #pragma unroll
        for (int i = 0; i < 4; i++) {
            int idx = tid + i * 256;
            int row = idx >> 3, f4 = idx & 7;
            pa[i] = *(const float4*)(Ab + (size_t)row * K + k0 + f4 * 4);
            pb[i] = *(const float4*)(Bb + (size_t)row * K + k0 + f4 * 4);
        }
    };
    auto sts = [&](int s) {
        uint32_t* Ah = hs + s * STG_U32;
        uint32_t* Al = Ah + 2560;
        uint32_t* Bh = Ah + 5120;
        uint32_t* Bl = Ah + 7680;
        #pragma unroll
        for (int i = 0; i < 4; i++) {
            int idx = tid + i * 256;
            int row = idx >> 3, f4 = idx & 7;
            int base = row * LDH + f4 * 2;
            uint32_t h0, h1, l0, l1;
            split4(pa[i], h0, h1, l0, l1);
            Ah[base] = h0; Ah[base + 1] = h1; Al[base] = l0; Al[base + 1] = l1;
            split4(pb[i], h0, h1, l0, l1);
            Bh[base] = h0; Bh[base + 1] = h1; Bl[base] = l0; Bl[base + 1] = l1;
        }
    };

    prefetch(0);
    sts(0);
    __syncthreads();

    float acc[2][8][4];
    #pragma unroll
    for (int mt = 0; mt < 2; mt++)
        #pragma unroll
        for (int nt = 0; nt < 8; nt++)
            #pragma unroll
            for (int i = 0; i < 4; i++) acc[mt][nt][i] = 0.f;

    int nk = K / 32;
    for (int kc = 0; kc < nk; kc++) {
        int buf = kc & 1;
        bool more = (kc + 1 < nk);
        if (more) prefetch((kc + 1) * 32);
        const uint32_t* Ah = hs + buf * STG_U32;
        const uint32_t* Al = Ah + 2560;
        const uint32_t* Bh = Ah + 5120;
        const uint32_t* Bl = Ah + 7680;
        #pragma unroll
        for (int ks = 0; ks < 2; ks++) {
            int ck = ks * 8;
            uint32_t ah[2][4], al_[2][4], bh[8][2], bl[8][2];
            #pragma unroll
            for (int mt = 0; mt < 2; mt++) {
                int mb = m_warp + mt * 16;
                int r0 = (mb + g) * LDH, r1 = (mb + 8 + g) * LDH;
                ah[mt][0] = Ah[r0 + ck + tg];     ah[mt][1] = Ah[r1 + ck + tg];
                ah[mt][2] = Ah[r0 + ck + tg + 4]; ah[mt][3] = Ah[r1 + ck + tg + 4];
                al_[mt][0] = Al[r0 + ck + tg];     al_[mt][1] = Al[r1 + ck + tg];
                al_[mt][2] = Al[r0 + ck + tg + 4]; al_[mt][3] = Al[r1 + ck + tg + 4];
            }
            #pragma unroll
            for (int nt = 0; nt < 8; nt++) {
                int rb = (n_warp + nt * 8 + g) * LDH;
                bh[nt][0] = Bh[rb + ck + tg]; bh[nt][1] = Bh[rb + ck + tg + 4];
                bl[nt][0] = Bl[rb + ck + tg]; bl[nt][1] = Bl[rb + ck + tg + 4];
            }
            if (ks == 1 && more) sts(buf ^ 1);
            #pragma unroll
            for (int mt = 0; mt < 2; mt++)
                #pragma unroll
                for (int nt = 0; nt < 8; nt++) {
                    mma_f16(acc[mt][nt], ah[mt], bh[nt]);
                    mma_f16(acc[mt][nt], ah[mt], bl[nt]);
                    mma_f16(acc[mt][nt], al_[mt], bh[nt]);
                }
        }
        __syncthreads();
    }

    float* Cb = C + (size_t)(blockIdx.y * 128 + m_warp) * N + blockIdx.x * 128 + n_warp;
    #pragma unroll
    for (int mt = 0; mt < 2; mt++)
        #pragma unroll
        for (int nt = 0; nt < 8; nt++) {
            int r0 = mt * 16 + g;
            int c0 = nt * 8 + 2 * tg;
            *(float2*)&Cb[(size_t)r0 * N + c0]       = make_float2(acc[mt][nt][0], acc[mt][nt][1]);
            *(float2*)&Cb[(size_t)(r0 + 8) * N + c0] = make_float2(acc[mt][nt][2], acc[mt][nt][3]);
        }
}

// ---------------- hyperbolic epilogue: vectorized + fused reductions ----------------
template<int N, bool DO_TANH>
__global__ void epi_kernel(const float* __restrict__ MX, const float* __restrict__ bvec,
                           const float* __restrict__ xn_in,
                           float* __restrict__ Xout, float* __restrict__ xn_out)
{
    constexpr int C = N / 256;
    __shared__ float red[24];
    int row = blockIdx.x, tid = threadIdx.x;
    const float* mx = MX + (size_t)row * N + tid * C;
    const float* bp = bvec + tid * C;
    float m[C], b[C];
    if (C == 4) {
        float4 mv = *(const float4*)mx; float4 bb = *(const float4*)bp;
        m[0] = mv.x; m[1 % C] = mv.y; m[2 % C] = mv.z; m[3 % C] = mv.w;
        b[0] = bb.x; b[1 % C] = bb.y; b[2 % C] = bb.z; b[3 % C] = bb.w;
    } else if (C == 2) {
        float2 mv = *(const float2*)mx; float2 bb = *(const float2*)bp;
        m[0] = mv.x; m[1 % C] = mv.y;
        b[0] = bb.x; b[1 % C] = bb.y;
    } else {
        m[0] = mx[0]; b[0] = bp[0];
    }
    float s_mm = 0.f, s_mb = 0.f, s_bb = 0.f;
    #pragma unroll
    for (int i = 0; i < C; i++) {
        s_mm += m[i] * m[i]; s_mb += m[i] * b[i]; s_bb += b[i] * b[i];
    }
    blockReduce3(s_mm, s_mb, s_bb, red);

    float xn  = fmaxf(xn_in[row], 1e-15f);
    float mxn = fmaxf(sqrtf(s_mm), 1e-15f);
    float t   = tanhf((mxn / xn) * atanhf(fminf(xn, ATANH_LIM)));
    float tc  = fminf(t, MAXNORM);
    float s1  = tc / mxn;
    float x2 = tc * tc, xy = s1 * s_mb, y2 = s_bb;
    float den = fmaxf(1.f + 2.f * xy + x2 * y2, 1e-15f);
    float ca = (1.f + 2.f * xy + y2) * s1 / den;
    float cb = (1.f - x2) / den;
    float s_zz = 0.f;
    #pragma unroll
    for (int i = 0; i < C; i++) { m[i] = ca * m[i] + cb * b[i]; s_zz += m[i] * m[i]; }
    s_zz = blockReduceSum(s_zz, red);
    float znp = sqrtf(s_zz);
    float zn  = fmaxf(znp, 1e-15f);
    float sc  = (zn > MAXNORM) ? (MAXNORM / zn) : 1.f;
    float outn = sc * znp;
    float* xo = Xout + (size_t)row * N + tid * C;
    float fsc;
    if (!DO_TANH) {
        fsc = sc;
        if (tid == 0) xn_out[row] = outn;
    } else {
        float nzn = fmaxf(outn, 1e-15f);
        float lsc = atanhf(fminf(nzn, ATANH_LIM)) / nzn * sc;
        float s_vv = 0.f;
        #pragma unroll
        for (int i = 0; i < C; i++) { m[i] = tanhf(lsc * m[i]); s_vv += m[i] * m[i]; }
        s_vv = blockReduceSum(s_vv, red);
        float vnp = sqrtf(s_vv);
        float vn  = fmaxf(vnp, 1e-15f);
        float esc = tanhf(vn) / vn;
        float en  = esc * vnp;
        float pn  = fmaxf(en, 1e-15f);
        float psc = (pn > MAXNORM) ? (MAXNORM / pn) : 1.f;
        fsc = psc * esc;
        if (tid == 0) xn_out[row] = fsc * vnp;
    }
    if (C == 4) {
        float4 v; v.x = fsc * m[0]; v.y = fsc * m[1 % C]; v.z = fsc * m[2 % C]; v.w = fsc * m[3 % C];
        *(float4*)xo = v;
    } else if (C == 2) {
        float2 v; v.x = fsc * m[0]; v.y = fsc * m[1 % C];
        *(float2*)xo = v;
    } else {
        xo[0] = fsc * m[0];
    }
}

// ---------------- mid = projx(mobius_add(0.27 (x) head, 0.73 (x) tail)) ----------------
__global__ void combine_kernel(const float* __restrict__ H, const float* __restrict__ Tl,
                               float* __restrict__ mid, float* __restrict__ midn)
{
    __shared__ float red[24];
    int row = blockIdx.x, tid = threadIdx.x;
    float h = H[(size_t)row * 256 + tid];
    float t = Tl[(size_t)row * 256 + tid];
    float shh = h * h, stt = t * t, sht = h * t;
    blockReduce3(shh, stt, sht, red);
    float hn = fmaxf(sqrtf(shh), 1e-15f);
    float tn = fmaxf(sqrtf(stt), 1e-15f);
    float th = tanhf(0.27f * atanhf(fminf(hn, ATANH_LIM)));
    float tt = tanhf(0.73f * atanhf(fminf(tn, ATANH_LIM)));
    float ah = th / hn, at = tt / tn;
    float x2 = th * th, y2 = tt * tt, xy = ah * at * sht;
    float den = fmaxf(1.f + 2.f * xy + x2 * y2, 1e-15f);
    float ca = (1.f + 2.f * xy + y2) * ah / den;
    float cb = (1.f - x2) * at / den;
    float z = ca * h + cb * t;
    float szz = blockReduceSum(z * z, red);
    float znp = sqrtf(szz);
    float zn  = fmaxf(znp, 1e-15f);
    float sc  = (zn > MAXNORM) ? (MAXNORM / zn) : 1.f;
    mid[(size_t)row * 256 + tid] = sc * z;
    if (tid == 0) midn[row] = sc * znp;
}

// ---------------- small MLP (256->64->32->2), one CTA handles 8 rows ----------------
__device__ void matvec_sm(const float* x, int K, const float* __restrict__ W, int n,
                          float* out, float* part)
{
    int tid = threadIdx.x;
    int col = tid % n;
    int q   = tid / n;
    int nch = 256 / n;
    float p = 0.f;
    for (int k = q; k < K; k += nch) p += x[k] * W[k * n + col];
    __syncthreads();
    part[tid] = p;
    __syncthreads();
    for (int s = nch / 2; s > 0; s >>= 1) {
        if (q < s) part[q * n + col] += part[(q + s) * n + col];
        __syncthreads();
    }
    if (tid < n) out[tid] = part[tid];
    __syncthreads();
}

__device__ float hlin_epi_sm(float* v, int n, const float* __restrict__ b, float xn,
                             bool do_tanh, float* red)
{
    int tid = threadIdx.x;
    float mi = (tid < n) ? v[tid] : 0.f;
    float bi = (tid < n) ? b[tid] : 0.f;
    float s_mm = mi * mi, s_mb = mi * bi, s_bb = bi * bi;
    blockReduce3(s_mm, s_mb, s_bb, red);
    xn = fmaxf(xn, 1e-15f);
    float mxn = fmaxf(sqrtf(s_mm), 1e-15f);
    float t  = tanhf((mxn / xn) * atanhf(fminf(xn, ATANH_LIM)));
    float tc = fminf(t, MAXNORM);
    float s1 = tc / mxn;
    float x2 = tc * tc, xy = s1 * s_mb, y2 = s_bb;
    float den = fmaxf(1.f + 2.f * xy + x2 * y2, 1e-15f);
    float ca = (1.f + 2.f * xy + y2) * s1 / den;
    float cb = (1.f - x2) / den;
    float z = ca * mi + cb * bi;
    float s_zz = blockReduceSum(z * z, red);
    float znp = sqrtf(s_zz), zn = fmaxf(znp, 1e-15f);
    float sc = (zn > MAXNORM) ? (MAXNORM / zn) : 1.f;
    float nn = sc * znp;
    if (do_tanh) {
        float nzn = fmaxf(nn, 1e-15f);
        float lsc = atanhf(fminf(nzn, ATANH_LIM)) / nzn * sc;
        float vi = tanhf(lsc * z);
        float s_vv = blockReduceSum(vi * vi, red);
        float vnp = sqrtf(s_vv), vn = fmaxf(vnp, 1e-15f);
        float esc = tanhf(vn) / vn;
        float en  = esc * vnp;
        float pn  = fmaxf(en, 1e-15f);
        float psc = (pn > MAXNORM) ? (MAXNORM / pn) : 1.f;
        if (tid < n) v[tid] = psc * esc * vi;
        nn = psc * esc * vnp;
    } else {
        if (tid < n) v[tid] = sc * z;
    }
    __syncthreads();
    return nn;
}

#define MLP_ROWS 8
__global__ void mlp_kernel(const float* __restrict__ mid, const float* __restrict__ midn,
                           const float* __restrict__ Wm1, const float* __restrict__ bm1,
                           const float* __restrict__ Wm2, const float* __restrict__ bm2,
                           const float* __restrict__ Wm3, const float* __restrict__ bm3,
                           float* __restrict__ out)
{
    __shared__ float sx[256];
    __shared__ float part[256];
    __shared__ float va[64];
    __shared__ float vb[32];
    __shared__ float vc[2];
    __shared__ float red[24];
    int tid = threadIdx.x;
    int r0 = blockIdx.x * MLP_ROWS;
    for (int r = r0; r < r0 + MLP_ROWS; r++) {
        sx[tid] = mid[(size_t)r * 256 + tid];
        float xn = midn[r];
        __syncthreads();
        matvec_sm(sx, 256, Wm1, 64, va, part);
        xn = hlin_epi_sm(va, 64, bm1, xn, true, red);
        matvec_sm(va, 64, Wm2, 32, vb, part);
        xn = hlin_epi_sm(vb, 32, bm2, xn, true, red);
        matvec_sm(vb, 32, Wm3, 2, vc, part);
        xn = hlin_epi_sm(vc, 2, bm3, xn, false, red);
        if (tid < 2) out[(size_t)r * 2 + tid] = vc[tid];
        __syncthreads();
    }
}

// ---------------- host orchestration ----------------
static void run_branch(const float* X, const float* W1t, const float* b1,
                       const float* W2t, const float* b2,
                       const float* W3t, const float* b3,
                       float* MX, float* Y, float* nrm)
{
    const int B = BATCH;
    hgemm<<<dim3(1024 / 128, B / 128), 256, HSMEM>>>(X, W1t, MX, 1024, KP1);
    epi_kernel<1024, true><<<B, 256>>>(MX, b1, nrm, Y, nrm);
    hgemm<<<dim3(512 / 128, B / 128), 256, HSMEM>>>(Y, W2t, MX, 512, 1024);
    epi_kernel<512, true><<<B, 256>>>(MX, b2, nrm, Y, nrm);
    hgemm<<<dim3(256 / 128, B / 128), 256, HSMEM>>>(Y, W3t, MX, 256, 512);
    epi_kernel<256, false><<<B, 256>>>(MX, b3, nrm, Y, nrm);
}

extern "C" void kernel_launch(void* const* d_in, const int* in_sizes, int n_in,
                              void* d_out, int out_size)
{
    const float* dcb  = (const float*)d_in[0];
    const float* dpc  = (const float*)d_in[1];
    const float* dmac = (const float*)d_in[2];
    const float* decf = (const float*)d_in[3];
    const float* tesm = (const float*)d_in[4];
    const float* tpc  = (const float*)d_in[5];
    const float* tmer = (const float*)d_in[6];
    const float* Wd1 = (const float*)d_in[7];  const float* bd1 = (const float*)d_in[8];
    const float* Wd2 = (const float*)d_in[9];  const float* bd2 = (const float*)d_in[10];
    const float* Wd3 = (const float*)d_in[11]; const float* bd3 = (const float*)d_in[12];
    const float* Wt1 = (const float*)d_in[13]; const float* bt1 = (const float*)d_in[14];
    const float* Wt2 = (const float*)d_in[15]; const float* bt2 = (const float*)d_in[16];
    const float* Wt3 = (const float*)d_in[17]; const float* bt3 = (const float*)d_in[18];
    const float* Wm1 = (const float*)d_in[19]; const float* bm1 = (const float*)d_in[20];
    const float* Wm2 = (const float*)d_in[21]; const float* bm2 = (const float*)d_in[22];
    const float* Wm3 = (const float*)d_in[23]; const float* bm3 = (const float*)d_in[24];

    float *Xd, *Xt, *MXd, *MXt, *Yd, *Yt, *nd, *nt, *mid, *nmid;
    float *Wd1t, *Wt1t, *Wd2t, *Wt2t, *Wd3t, *Wt3t;
    cudaGetSymbolAddress((void**)&Xd,   g_Xd);
    cudaGetSymbolAddress((void**)&Xt,   g_Xt);
    cudaGetSymbolAddress((void**)&MXd,  g_MXd);
    cudaGetSymbolAddress((void**)&MXt,  g_MXt);
    cudaGetSymbolAddress((void**)&Yd,   g_Yd);
    cudaGetSymbolAddress((void**)&Yt,   g_Yt);
    cudaGetSymbolAddress((void**)&nd,   g_nd);
    cudaGetSymbolAddress((void**)&nt,   g_nt);
    cudaGetSymbolAddress((void**)&mid,  g_mid);
    cudaGetSymbolAddress((void**)&nmid, g_nmid);
    cudaGetSymbolAddress((void**)&Wd1t, g_Wd1t);
    cudaGetSymbolAddress((void**)&Wt1t, g_Wt1t);
    cudaGetSymbolAddress((void**)&Wd2t, g_Wd2t);
    cudaGetSymbolAddress((void**)&Wt2t, g_Wt2t);
    cudaGetSymbolAddress((void**)&Wd3t, g_Wd3t);
    cudaGetSymbolAddress((void**)&Wt3t, g_Wt3t);

    cudaFuncSetAttribute(hgemm, cudaFuncAttributeMaxDynamicSharedMemorySize, HSMEM);

    const int B = BATCH;
    dim3 tb(32, 8);
    transpose_pad<<<dim3(KP1 / 32, 1024 / 32), tb>>>(Wd1, Wd1t, D_IN, 1024, KP1);
    transpose_pad<<<dim3(KP1 / 32, 1024 / 32), tb>>>(Wt1, Wt1t, D_IN, 1024, KP1);
    transpose_pad<<<dim3(1024 / 32, 512 / 32), tb>>>(Wd2, Wd2t, 1024, 512, 1024);
    transpose_pad<<<dim3(1024 / 32, 512 / 32), tb>>>(Wt2, Wt2t, 1024, 512, 1024);
    transpose_pad<<<dim3(512 / 32, 256 / 32), tb>>>(Wd3, Wd3t, 512, 256, 512);
    transpose_pad<<<dim3(512 / 32, 256 / 32), tb>>>(Wt3, Wt3t, 512, 256, 512);

    pre_kernel<<<B, 256>>>(dcb, 768, dpc, 11, dmac, 167, decf, 765, Xd, nd);
    pre_kernel<<<B, 256>>>(tesm, 1280, tpc, 11, tmer, 420, nullptr, 0, Xt, nt);

    run_branch(Xd, Wd1t, bd1, Wd2t, bd2, Wd3t, bd3, MXd, Yd, nd);
    run_branch(Xt, Wt1t, bt1, Wt2t, bt2, Wt3t, bt3, MXt, Yt, nt);

    combine_kernel<<<B, 256>>>(Yd, Yt, mid, nmid);

    mlp_kernel<<<B / MLP_ROWS, 256>>>(mid, nmid, Wm1, bm1, Wm2, bm2, Wm3, bm3,
                                      (float*)d_out);
}